// round 1
// baseline (speedup 1.0000x reference)
#include <cuda_runtime.h>
#include <cstdint>

// LightGCN 2-hop smoothing.
// N = NU + NI nodes (200k), d = 64, E = 1.25M undirected edges.
// out = (2*x0 + 2*x1 + x2) / 3, x1 = S x0, x2 = S x1, S = D^-1/2 A D^-1/2.

#define EMB 64
#define MAX_NODES 200000

// Scratch (allocation-free rule: __device__ globals).
__device__ float g_dis[MAX_NODES];                       // degree, then deg^-1/2
__device__ float g_x1[(size_t)MAX_NODES * EMB];          // first smoothing result

__global__ void zero_kernel(int n_nodes) {
    size_t tot = (size_t)n_nodes * EMB;
    size_t stride = (size_t)gridDim.x * blockDim.x;
    for (size_t k = (size_t)blockIdx.x * blockDim.x + threadIdx.x; k < tot; k += stride) {
        g_x1[k] = 0.0f;
        if (k < (size_t)n_nodes) g_dis[k] = 0.0f;
    }
}

__global__ void deg_kernel(const int* __restrict__ u_idx,
                           const int* __restrict__ i_idx,
                           int E, int NU) {
    int e = blockIdx.x * blockDim.x + threadIdx.x;
    if (e < E) {
        atomicAdd(&g_dis[u_idx[e]], 1.0f);
        atomicAdd(&g_dis[NU + i_idx[e]], 1.0f);
    }
}

__global__ void inv_sqrt_kernel(int N) {
    int n = blockIdx.x * blockDim.x + threadIdx.x;
    if (n < N) {
        float d = g_dis[n];
        g_dis[n] = (d > 0.0f) ? rsqrtf(d) : 0.0f;
    }
}

// Pass 1: x1[dst] += w * x0[src], both directions per undirected edge.
// One warp per edge; each lane handles a float2 (64 dims / 32 lanes).
__global__ void smooth1_kernel(const float* __restrict__ u_emb,
                               const float* __restrict__ i_emb,
                               const int* __restrict__ u_idx,
                               const int* __restrict__ i_idx,
                               int E, int NU) {
    int warp = (int)(((size_t)blockIdx.x * blockDim.x + threadIdx.x) >> 5);
    int lane = threadIdx.x & 31;
    if (warp >= E) return;

    int u  = u_idx[warp];
    int iv = i_idx[warp];
    int g  = NU + iv;

    float w = g_dis[u] * g_dis[g];

    float2 au = ((const float2*)(u_emb + (size_t)u  * EMB))[lane];
    float2 ag = ((const float2*)(i_emb + (size_t)iv * EMB))[lane];

    float* x1g = g_x1 + (size_t)g * EMB + 2 * lane;
    float* x1u = g_x1 + (size_t)u * EMB + 2 * lane;
    atomicAdd(x1g,     w * au.x);
    atomicAdd(x1g + 1, w * au.y);
    atomicAdd(x1u,     w * ag.x);
    atomicAdd(x1u + 1, w * ag.y);
}

// out = (2*x0 + 2*x1) / 3   (x2/3 is scattered into out by smooth2)
__global__ void out_init_kernel(const float* __restrict__ u_emb,
                                const float* __restrict__ i_emb,
                                float* __restrict__ out,
                                int N, int NU) {
    size_t tot = (size_t)N * EMB;
    size_t u_tot = (size_t)NU * EMB;
    size_t stride = (size_t)gridDim.x * blockDim.x;
    const float inv3 = 1.0f / 3.0f;
    for (size_t k = (size_t)blockIdx.x * blockDim.x + threadIdx.x; k < tot; k += stride) {
        float x0 = (k < u_tot) ? u_emb[k] : i_emb[k - u_tot];
        out[k] = (2.0f * x0 + 2.0f * g_x1[k]) * inv3;
    }
}

// Pass 2: out[dst] += (w/3) * x1[src], both directions.
__global__ void smooth2_kernel(const int* __restrict__ u_idx,
                               const int* __restrict__ i_idx,
                               float* __restrict__ out,
                               int E, int NU) {
    int warp = (int)(((size_t)blockIdx.x * blockDim.x + threadIdx.x) >> 5);
    int lane = threadIdx.x & 31;
    if (warp >= E) return;

    int u  = u_idx[warp];
    int g  = NU + i_idx[warp];

    float w = g_dis[u] * g_dis[g] * (1.0f / 3.0f);

    float2 au = ((const float2*)(g_x1 + (size_t)u * EMB))[lane];
    float2 ag = ((const float2*)(g_x1 + (size_t)g * EMB))[lane];

    float* og = out + (size_t)g * EMB + 2 * lane;
    float* ou = out + (size_t)u * EMB + 2 * lane;
    atomicAdd(og,     w * au.x);
    atomicAdd(og + 1, w * au.y);
    atomicAdd(ou,     w * ag.x);
    atomicAdd(ou + 1, w * ag.y);
}

extern "C" void kernel_launch(void* const* d_in, const int* in_sizes, int n_in,
                              void* d_out, int out_size) {
    const float* u_emb = (const float*)d_in[0];
    const float* i_emb = (const float*)d_in[1];
    const int*   u_idx = (const int*)d_in[2];
    const int*   i_idx = (const int*)d_in[3];
    float*       out   = (float*)d_out;

    int NU = in_sizes[0] / EMB;
    int NI = in_sizes[1] / EMB;
    int E  = in_sizes[2];
    int N  = NU + NI;

    // 1. zero scratch
    {
        int threads = 256;
        int blocks = 2048;
        zero_kernel<<<blocks, threads>>>(N);
    }
    // 2. degrees
    deg_kernel<<<(E + 255) / 256, 256>>>(u_idx, i_idx, E, NU);
    // 3. deg^-1/2
    inv_sqrt_kernel<<<(N + 255) / 256, 256>>>(N);
    // 4. x1 = S x0
    {
        size_t threads_total = (size_t)E * 32;
        int blocks = (int)((threads_total + 255) / 256);
        smooth1_kernel<<<blocks, 256>>>(u_emb, i_emb, u_idx, i_idx, E, NU);
    }
    // 5. out = (2 x0 + 2 x1)/3
    out_init_kernel<<<2048, 256>>>(u_emb, i_emb, out, N, NU);
    // 6. out += (S x1)/3
    {
        size_t threads_total = (size_t)E * 32;
        int blocks = (int)((threads_total + 255) / 256);
        smooth2_kernel<<<blocks, 256>>>(u_idx, i_idx, out, E, NU);
    }
}

// round 2
// speedup vs baseline: 1.1645x; 1.1645x over previous
#include <cuda_runtime.h>
#include <cstdint>

// LightGCN 2-hop smoothing.
// N = NU + NI nodes (200k), d = 64, E = 1.25M undirected edges.
// out = (2*x0 + 2*x1 + x2) / 3, x1 = S x0, x2 = S x1, S = D^-1/2 A D^-1/2.

#define EMB 64
#define MAX_NODES 200000

__device__ float g_dis[MAX_NODES];                 // degree, then deg^-1/2
__device__ float g_x1[(size_t)MAX_NODES * EMB];    // first smoothing result

__global__ void zero_kernel(int n_nodes) {
    size_t tot4 = (size_t)n_nodes * (EMB / 4);
    size_t stride = (size_t)gridDim.x * blockDim.x;
    float4 z = make_float4(0.f, 0.f, 0.f, 0.f);
    for (size_t k = (size_t)blockIdx.x * blockDim.x + threadIdx.x; k < tot4; k += stride) {
        ((float4*)g_x1)[k] = z;
        if (k < (size_t)n_nodes) g_dis[k] = 0.0f;
    }
}

__global__ void deg_kernel(const int* __restrict__ u_idx,
                           const int* __restrict__ i_idx,
                           int E, int NU) {
    int e = blockIdx.x * blockDim.x + threadIdx.x;
    if (e < E) {
        atomicAdd(&g_dis[u_idx[e]], 1.0f);
        atomicAdd(&g_dis[NU + i_idx[e]], 1.0f);
    }
}

__global__ void inv_sqrt_kernel(int N) {
    int n = blockIdx.x * blockDim.x + threadIdx.x;
    if (n < N) {
        float d = g_dis[n];
        g_dis[n] = (d > 0.0f) ? rsqrtf(d) : 0.0f;
    }
}

// Pass 1: x1[dst] += w * x0[src], both directions per undirected edge.
// One warp per edge. Lanes 0-15: u -> g (item side); lanes 16-31: g -> u.
// Each lane moves one float4 (16 lanes * 4 = 64 dims) with ONE vector atomic.
__global__ void smooth1_kernel(const float* __restrict__ u_emb,
                               const float* __restrict__ i_emb,
                               const int* __restrict__ u_idx,
                               const int* __restrict__ i_idx,
                               int E, int NU) {
    int warp = (int)(((size_t)blockIdx.x * blockDim.x + threadIdx.x) >> 5);
    int lane = threadIdx.x & 31;
    if (warp >= E) return;

    int u  = u_idx[warp];
    int iv = i_idx[warp];
    int g  = NU + iv;

    float w = g_dis[u] * g_dis[g];

    int half = lane >> 4;        // 0: u->g, 1: g->u
    int c    = lane & 15;        // float4 chunk index

    const float4* srcp = half
        ? (const float4*)(i_emb + (size_t)iv * EMB)
        : (const float4*)(u_emb + (size_t)u  * EMB);
    float4* dstp = half
        ? (float4*)(g_x1 + (size_t)u * EMB)
        : (float4*)(g_x1 + (size_t)g * EMB);

    float4 a = srcp[c];
    float4 m = make_float4(w * a.x, w * a.y, w * a.z, w * a.w);
    atomicAdd(&dstp[c], m);
}

// out = (2*x0 + 2*x1) / 3   (x2/3 is scattered into out by smooth2)
__global__ void out_init_kernel(const float* __restrict__ u_emb,
                                const float* __restrict__ i_emb,
                                float* __restrict__ out,
                                int N, int NU) {
    size_t tot4   = (size_t)N  * (EMB / 4);
    size_t u_tot4 = (size_t)NU * (EMB / 4);
    size_t stride = (size_t)gridDim.x * blockDim.x;
    const float c23 = 2.0f / 3.0f;
    for (size_t k = (size_t)blockIdx.x * blockDim.x + threadIdx.x; k < tot4; k += stride) {
        float4 x0 = (k < u_tot4) ? ((const float4*)u_emb)[k]
                                 : ((const float4*)i_emb)[k - u_tot4];
        float4 x1 = ((const float4*)g_x1)[k];
        float4 o;
        o.x = c23 * (x0.x + x1.x);
        o.y = c23 * (x0.y + x1.y);
        o.z = c23 * (x0.z + x1.z);
        o.w = c23 * (x0.w + x1.w);
        ((float4*)out)[k] = o;
    }
}

// Pass 2: out[dst] += (w/3) * x1[src], both directions. Same float4 scheme.
__global__ void smooth2_kernel(const int* __restrict__ u_idx,
                               const int* __restrict__ i_idx,
                               float* __restrict__ out,
                               int E, int NU) {
    int warp = (int)(((size_t)blockIdx.x * blockDim.x + threadIdx.x) >> 5);
    int lane = threadIdx.x & 31;
    if (warp >= E) return;

    int u = u_idx[warp];
    int g = NU + i_idx[warp];

    float w = g_dis[u] * g_dis[g] * (1.0f / 3.0f);

    int half = lane >> 4;
    int c    = lane & 15;

    const float4* srcp = half
        ? (const float4*)(g_x1 + (size_t)g * EMB)
        : (const float4*)(g_x1 + (size_t)u * EMB);
    float4* dstp = half
        ? (float4*)(out + (size_t)u * EMB)
        : (float4*)(out + (size_t)g * EMB);

    float4 a = srcp[c];
    float4 m = make_float4(w * a.x, w * a.y, w * a.z, w * a.w);
    atomicAdd(&dstp[c], m);
}

extern "C" void kernel_launch(void* const* d_in, const int* in_sizes, int n_in,
                              void* d_out, int out_size) {
    const float* u_emb = (const float*)d_in[0];
    const float* i_emb = (const float*)d_in[1];
    const int*   u_idx = (const int*)d_in[2];
    const int*   i_idx = (const int*)d_in[3];
    float*       out   = (float*)d_out;

    int NU = in_sizes[0] / EMB;
    int NI = in_sizes[1] / EMB;
    int E  = in_sizes[2];
    int N  = NU + NI;

    zero_kernel<<<2048, 256>>>(N);
    deg_kernel<<<(E + 255) / 256, 256>>>(u_idx, i_idx, E, NU);
    inv_sqrt_kernel<<<(N + 255) / 256, 256>>>(N);
    {
        size_t threads_total = (size_t)E * 32;
        int blocks = (int)((threads_total + 255) / 256);
        smooth1_kernel<<<blocks, 256>>>(u_emb, i_emb, u_idx, i_idx, E, NU);
    }
    out_init_kernel<<<2048, 256>>>(u_emb, i_emb, out, N, NU);
    {
        size_t threads_total = (size_t)E * 32;
        int blocks = (int)((threads_total + 255) / 256);
        smooth2_kernel<<<blocks, 256>>>(u_idx, i_idx, out, E, NU);
    }
}

// round 3
// speedup vs baseline: 1.9595x; 1.6826x over previous
#include <cuda_runtime.h>
#include <cstdint>

// LightGCN 2-hop smoothing, pull-based SpMM over an on-the-fly CSR.
// N = NU + NI (200k), d = 64, E = 1.25M undirected (2.5M directed).
// out = (2*x0 + 2*x1 + x2)/3, x1 = S x0, x2 = S x1, S = D^-1/2 A D^-1/2.
// x1[n] = dis[n] * sum_{s in N(n)} dis[s] * x0[s]

#define EMB 64
#define MAX_NODES 200000
#define MAX_DEDGES 2500000
#define SCAN_B 256
#define MAX_SCAN_BLOCKS 1024   // ceil(200000/256) = 782

__device__ int   g_deg[MAX_NODES];
__device__ float g_dis[MAX_NODES];
__device__ int   g_row[MAX_NODES + 1];
__device__ int   g_cursor[MAX_NODES];
__device__ int   g_bsums[MAX_SCAN_BLOCKS];
__device__ int   g_boff[MAX_SCAN_BLOCKS];
__device__ int   g_adj[MAX_DEDGES];
__device__ float g_x1[(size_t)MAX_NODES * EMB];

__global__ void zero_deg_kernel(int N) {
    int n = blockIdx.x * blockDim.x + threadIdx.x;
    if (n < N) g_deg[n] = 0;
}

__global__ void deg_kernel(const int* __restrict__ u_idx,
                           const int* __restrict__ i_idx,
                           int E, int NU) {
    int e = blockIdx.x * blockDim.x + threadIdx.x;
    if (e < E) {
        atomicAdd(&g_deg[u_idx[e]], 1);
        atomicAdd(&g_deg[NU + i_idx[e]], 1);
    }
}

__global__ void dis_kernel(int N) {
    int n = blockIdx.x * blockDim.x + threadIdx.x;
    if (n < N) {
        int d = g_deg[n];
        g_dis[n] = (d > 0) ? rsqrtf((float)d) : 0.0f;
    }
}

// ---- prefix scan (exclusive) of g_deg into g_row ----

__global__ void scan1_kernel(int N) {
    __shared__ int sh[SCAN_B];
    int t = threadIdx.x;
    int idx = blockIdx.x * SCAN_B + t;
    int v = (idx < N) ? g_deg[idx] : 0;
    sh[t] = v;
    __syncthreads();
    for (int off = 1; off < SCAN_B; off <<= 1) {
        int tmp = (t >= off) ? sh[t - off] : 0;
        __syncthreads();
        sh[t] += tmp;
        __syncthreads();
    }
    int incl = sh[t];
    if (idx < N) g_row[idx] = incl - v;   // block-local exclusive
    if (t == SCAN_B - 1) g_bsums[blockIdx.x] = incl;
}

__global__ void scan2_kernel(int nblocks) {
    __shared__ int sh[MAX_SCAN_BLOCKS];
    int t = threadIdx.x;
    int v = (t < nblocks) ? g_bsums[t] : 0;
    sh[t] = v;
    __syncthreads();
    for (int off = 1; off < MAX_SCAN_BLOCKS; off <<= 1) {
        int tmp = (t >= off) ? sh[t - off] : 0;
        __syncthreads();
        sh[t] += tmp;
        __syncthreads();
    }
    if (t < nblocks) g_boff[t] = sh[t] - v;  // exclusive
}

__global__ void scan3_kernel(int N, int twoE) {
    int idx = blockIdx.x * SCAN_B + threadIdx.x;
    if (idx < N) {
        int r = g_row[idx] + g_boff[blockIdx.x];
        g_row[idx] = r;
        g_cursor[idx] = r;
    }
    if (idx == 0) g_row[N] = twoE;
}

__global__ void fill_kernel(const int* __restrict__ u_idx,
                            const int* __restrict__ i_idx,
                            int E, int NU) {
    int e = blockIdx.x * blockDim.x + threadIdx.x;
    if (e < E) {
        int u = u_idx[e];
        int g = NU + i_idx[e];
        g_adj[atomicAdd(&g_cursor[g], 1)] = u;
        g_adj[atomicAdd(&g_cursor[u], 1)] = g;
    }
}

// ---- pull pass 1: x1 = S x0 (x0 split across u_emb / i_emb) ----
// One warp per node; lane holds float2 of the 64-dim accumulator.
__global__ void pull1_kernel(const float* __restrict__ u_emb,
                             const float* __restrict__ i_emb,
                             int N, int NU) {
    int warp = (int)(((size_t)blockIdx.x * blockDim.x + threadIdx.x) >> 5);
    int lane = threadIdx.x & 31;
    if (warp >= N) return;

    int start = g_row[warp];
    int end   = g_row[warp + 1];

    float2 acc = make_float2(0.0f, 0.0f);
    int k = start;
    for (; k + 1 < end; k += 2) {
        int s0 = g_adj[k];
        int s1 = g_adj[k + 1];
        float w0 = g_dis[s0];
        float w1 = g_dis[s1];
        const float* b0 = (s0 < NU) ? (u_emb + (size_t)s0 * EMB)
                                    : (i_emb + (size_t)(s0 - NU) * EMB);
        const float* b1 = (s1 < NU) ? (u_emb + (size_t)s1 * EMB)
                                    : (i_emb + (size_t)(s1 - NU) * EMB);
        float2 v0 = ((const float2*)b0)[lane];
        float2 v1 = ((const float2*)b1)[lane];
        acc.x += w0 * v0.x + w1 * v1.x;
        acc.y += w0 * v0.y + w1 * v1.y;
    }
    if (k < end) {
        int s = g_adj[k];
        float w = g_dis[s];
        const float* b = (s < NU) ? (u_emb + (size_t)s * EMB)
                                  : (i_emb + (size_t)(s - NU) * EMB);
        float2 v = ((const float2*)b)[lane];
        acc.x += w * v.x;
        acc.y += w * v.y;
    }

    float dn = g_dis[warp];
    ((float2*)(g_x1 + (size_t)warp * EMB))[lane] =
        make_float2(dn * acc.x, dn * acc.y);
}

// ---- pull pass 2 fused with output combine ----
// out[n] = (2*x0[n] + 2*x1[n] + dis[n]*sum dis[s]*x1[s]) / 3
__global__ void pull2_kernel(const float* __restrict__ u_emb,
                             const float* __restrict__ i_emb,
                             float* __restrict__ out,
                             int N, int NU) {
    int warp = (int)(((size_t)blockIdx.x * blockDim.x + threadIdx.x) >> 5);
    int lane = threadIdx.x & 31;
    if (warp >= N) return;

    int start = g_row[warp];
    int end   = g_row[warp + 1];

    float2 acc = make_float2(0.0f, 0.0f);
    int k = start;
    for (; k + 1 < end; k += 2) {
        int s0 = g_adj[k];
        int s1 = g_adj[k + 1];
        float w0 = g_dis[s0];
        float w1 = g_dis[s1];
        float2 v0 = ((const float2*)(g_x1 + (size_t)s0 * EMB))[lane];
        float2 v1 = ((const float2*)(g_x1 + (size_t)s1 * EMB))[lane];
        acc.x += w0 * v0.x + w1 * v1.x;
        acc.y += w0 * v0.y + w1 * v1.y;
    }
    if (k < end) {
        int s = g_adj[k];
        float w = g_dis[s];
        float2 v = ((const float2*)(g_x1 + (size_t)s * EMB))[lane];
        acc.x += w * v.x;
        acc.y += w * v.y;
    }

    float dn = g_dis[warp];
    const float* x0b = (warp < NU) ? (u_emb + (size_t)warp * EMB)
                                   : (i_emb + (size_t)(warp - NU) * EMB);
    float2 x0v = ((const float2*)x0b)[lane];
    float2 x1v = ((const float2*)(g_x1 + (size_t)warp * EMB))[lane];

    const float inv3 = 1.0f / 3.0f;
    float2 o;
    o.x = (2.0f * x0v.x + 2.0f * x1v.x + dn * acc.x) * inv3;
    o.y = (2.0f * x0v.y + 2.0f * x1v.y + dn * acc.y) * inv3;
    ((float2*)(out + (size_t)warp * EMB))[lane] = o;
}

extern "C" void kernel_launch(void* const* d_in, const int* in_sizes, int n_in,
                              void* d_out, int out_size) {
    const float* u_emb = (const float*)d_in[0];
    const float* i_emb = (const float*)d_in[1];
    const int*   u_idx = (const int*)d_in[2];
    const int*   i_idx = (const int*)d_in[3];
    float*       out   = (float*)d_out;

    int NU = in_sizes[0] / EMB;
    int NI = in_sizes[1] / EMB;
    int E  = in_sizes[2];
    int N  = NU + NI;

    int nScanBlocks = (N + SCAN_B - 1) / SCAN_B;

    zero_deg_kernel<<<(N + 255) / 256, 256>>>(N);
    deg_kernel<<<(E + 255) / 256, 256>>>(u_idx, i_idx, E, NU);
    dis_kernel<<<(N + 255) / 256, 256>>>(N);

    scan1_kernel<<<nScanBlocks, SCAN_B>>>(N);
    scan2_kernel<<<1, MAX_SCAN_BLOCKS>>>(nScanBlocks);
    scan3_kernel<<<nScanBlocks, SCAN_B>>>(N, 2 * E);

    fill_kernel<<<(E + 255) / 256, 256>>>(u_idx, i_idx, E, NU);

    {
        size_t threads_total = (size_t)N * 32;
        int blocks = (int)((threads_total + 255) / 256);
        pull1_kernel<<<blocks, 256>>>(u_emb, i_emb, N, NU);
        pull2_kernel<<<blocks, 256>>>(u_emb, i_emb, out, N, NU);
    }
}

// round 4
// speedup vs baseline: 2.1601x; 1.1024x over previous
#include <cuda_runtime.h>
#include <cstdint>

// LightGCN 2-hop smoothing, pull-based SpMM over an on-the-fly CSR.
// N = NU + NI (200k), d = 64, E = 1.25M undirected (2.5M directed).
// out = (2*x0 + 2*x1 + x2)/3, x1 = S x0, x2 = S x1, S = D^-1/2 A D^-1/2.
// x1[n] = dis[n] * sum_{s in N(n)} dis[s] * x0[s]

#define EMB 64
#define MAX_NODES 200000
#define MAX_DEDGES 2500000
#define SCAN_B 256
#define MAX_SCAN_BLOCKS 1024   // ceil(200000/256) = 782

__device__ int   g_deg[MAX_NODES];
__device__ float g_dis[MAX_NODES];
__device__ int   g_row[MAX_NODES + 1];
__device__ int   g_cursor[MAX_NODES];
__device__ int   g_bsums[MAX_SCAN_BLOCKS];
__device__ int   g_boff[MAX_SCAN_BLOCKS];
__device__ int   g_adj[MAX_DEDGES];
__device__ float g_x1[(size_t)MAX_NODES * EMB];

__global__ void zero_deg_kernel(int N) {
    int n = blockIdx.x * blockDim.x + threadIdx.x;
    if (n < N) g_deg[n] = 0;
}

__global__ void deg_kernel(const int* __restrict__ u_idx,
                           const int* __restrict__ i_idx,
                           int E, int NU) {
    int e = blockIdx.x * blockDim.x + threadIdx.x;
    if (e < E) {
        atomicAdd(&g_deg[u_idx[e]], 1);
        atomicAdd(&g_deg[NU + i_idx[e]], 1);
    }
}

__global__ void dis_kernel(int N) {
    int n = blockIdx.x * blockDim.x + threadIdx.x;
    if (n < N) {
        int d = g_deg[n];
        g_dis[n] = (d > 0) ? rsqrtf((float)d) : 0.0f;
    }
}

// ---- prefix scan (exclusive) of g_deg into g_row ----

__global__ void scan1_kernel(int N) {
    __shared__ int sh[SCAN_B];
    int t = threadIdx.x;
    int idx = blockIdx.x * SCAN_B + t;
    int v = (idx < N) ? g_deg[idx] : 0;
    sh[t] = v;
    __syncthreads();
    for (int off = 1; off < SCAN_B; off <<= 1) {
        int tmp = (t >= off) ? sh[t - off] : 0;
        __syncthreads();
        sh[t] += tmp;
        __syncthreads();
    }
    int incl = sh[t];
    if (idx < N) g_row[idx] = incl - v;   // block-local exclusive
    if (t == SCAN_B - 1) g_bsums[blockIdx.x] = incl;
}

__global__ void scan2_kernel(int nblocks) {
    __shared__ int sh[MAX_SCAN_BLOCKS];
    int t = threadIdx.x;
    int v = (t < nblocks) ? g_bsums[t] : 0;
    sh[t] = v;
    __syncthreads();
    for (int off = 1; off < MAX_SCAN_BLOCKS; off <<= 1) {
        int tmp = (t >= off) ? sh[t - off] : 0;
        __syncthreads();
        sh[t] += tmp;
        __syncthreads();
    }
    if (t < nblocks) g_boff[t] = sh[t] - v;  // exclusive
}

__global__ void scan3_kernel(int N, int twoE) {
    int idx = blockIdx.x * SCAN_B + threadIdx.x;
    if (idx < N) {
        int r = g_row[idx] + g_boff[blockIdx.x];
        g_row[idx] = r;
        g_cursor[idx] = r;
    }
    if (idx == 0) g_row[N] = twoE;
}

__global__ void fill_kernel(const int* __restrict__ u_idx,
                            const int* __restrict__ i_idx,
                            int E, int NU) {
    int e = blockIdx.x * blockDim.x + threadIdx.x;
    if (e < E) {
        int u = u_idx[e];
        int g = NU + i_idx[e];
        g_adj[atomicAdd(&g_cursor[g], 1)] = u;
        g_adj[atomicAdd(&g_cursor[u], 1)] = g;
    }
}

// ---- pull pass 1: x1 = S x0 ----
// One warp per node. Half-warps process different neighbors; each lane holds
// one float4 (16 lanes x 16B = full 256B row). Unroll x2 -> 4 neighbors/iter.
__global__ void pull1_kernel(const float* __restrict__ u_emb,
                             const float* __restrict__ i_emb,
                             int N, int NU) {
    int warp = (int)(((size_t)blockIdx.x * blockDim.x + threadIdx.x) >> 5);
    int lane = threadIdx.x & 31;
    if (warp >= N) return;

    int half = lane >> 4;   // 0 or 1: which neighbor within the pair
    int q    = lane & 15;   // float4 chunk index within the row

    int start = g_row[warp];
    int end   = g_row[warp + 1];

    float4 acc = make_float4(0.f, 0.f, 0.f, 0.f);
    int k = start;

    for (; k + 3 < end; k += 4) {
        int sA = g_adj[k + half];
        int sB = g_adj[k + 2 + half];
        float wA = g_dis[sA];
        float wB = g_dis[sB];
        const float4* pA = (sA < NU) ? (const float4*)(u_emb + (size_t)sA * EMB)
                                     : (const float4*)(i_emb + (size_t)(sA - NU) * EMB);
        const float4* pB = (sB < NU) ? (const float4*)(u_emb + (size_t)sB * EMB)
                                     : (const float4*)(i_emb + (size_t)(sB - NU) * EMB);
        float4 vA = pA[q];
        float4 vB = pB[q];
        acc.x += wA * vA.x + wB * vB.x;
        acc.y += wA * vA.y + wB * vB.y;
        acc.z += wA * vA.z + wB * vB.z;
        acc.w += wA * vA.w + wB * vB.w;
    }
    if (k + 1 < end) {
        int s = g_adj[k + half];
        float w = g_dis[s];
        const float4* p = (s < NU) ? (const float4*)(u_emb + (size_t)s * EMB)
                                   : (const float4*)(i_emb + (size_t)(s - NU) * EMB);
        float4 v = p[q];
        acc.x += w * v.x; acc.y += w * v.y; acc.z += w * v.z; acc.w += w * v.w;
        k += 2;
    }
    if (k < end && half == 0) {
        int s = g_adj[k];
        float w = g_dis[s];
        const float4* p = (s < NU) ? (const float4*)(u_emb + (size_t)s * EMB)
                                   : (const float4*)(i_emb + (size_t)(s - NU) * EMB);
        float4 v = p[q];
        acc.x += w * v.x; acc.y += w * v.y; acc.z += w * v.z; acc.w += w * v.w;
    }

    // combine halves
    acc.x += __shfl_xor_sync(0xffffffffu, acc.x, 16);
    acc.y += __shfl_xor_sync(0xffffffffu, acc.y, 16);
    acc.z += __shfl_xor_sync(0xffffffffu, acc.z, 16);
    acc.w += __shfl_xor_sync(0xffffffffu, acc.w, 16);

    if (half == 0) {
        float dn = g_dis[warp];
        float4 o = make_float4(dn * acc.x, dn * acc.y, dn * acc.z, dn * acc.w);
        ((float4*)(g_x1 + (size_t)warp * EMB))[q] = o;
    }
}

// ---- pull pass 2 fused with output combine ----
// out[n] = (2*x0[n] + 2*x1[n] + dis[n]*sum dis[s]*x1[s]) / 3
__global__ void pull2_kernel(const float* __restrict__ u_emb,
                             const float* __restrict__ i_emb,
                             float* __restrict__ out,
                             int N, int NU) {
    int warp = (int)(((size_t)blockIdx.x * blockDim.x + threadIdx.x) >> 5);
    int lane = threadIdx.x & 31;
    if (warp >= N) return;

    int half = lane >> 4;
    int q    = lane & 15;

    int start = g_row[warp];
    int end   = g_row[warp + 1];

    float4 acc = make_float4(0.f, 0.f, 0.f, 0.f);
    int k = start;

    for (; k + 3 < end; k += 4) {
        int sA = g_adj[k + half];
        int sB = g_adj[k + 2 + half];
        float wA = g_dis[sA];
        float wB = g_dis[sB];
        float4 vA = ((const float4*)(g_x1 + (size_t)sA * EMB))[q];
        float4 vB = ((const float4*)(g_x1 + (size_t)sB * EMB))[q];
        acc.x += wA * vA.x + wB * vB.x;
        acc.y += wA * vA.y + wB * vB.y;
        acc.z += wA * vA.z + wB * vB.z;
        acc.w += wA * vA.w + wB * vB.w;
    }
    if (k + 1 < end) {
        int s = g_adj[k + half];
        float w = g_dis[s];
        float4 v = ((const float4*)(g_x1 + (size_t)s * EMB))[q];
        acc.x += w * v.x; acc.y += w * v.y; acc.z += w * v.z; acc.w += w * v.w;
        k += 2;
    }
    if (k < end && half == 0) {
        int s = g_adj[k];
        float w = g_dis[s];
        float4 v = ((const float4*)(g_x1 + (size_t)s * EMB))[q];
        acc.x += w * v.x; acc.y += w * v.y; acc.z += w * v.z; acc.w += w * v.w;
    }

    acc.x += __shfl_xor_sync(0xffffffffu, acc.x, 16);
    acc.y += __shfl_xor_sync(0xffffffffu, acc.y, 16);
    acc.z += __shfl_xor_sync(0xffffffffu, acc.z, 16);
    acc.w += __shfl_xor_sync(0xffffffffu, acc.w, 16);

    if (half == 0) {
        float dn = g_dis[warp];
        const float4* x0b = (warp < NU)
            ? (const float4*)(u_emb + (size_t)warp * EMB)
            : (const float4*)(i_emb + (size_t)(warp - NU) * EMB);
        float4 x0v = x0b[q];
        float4 x1v = ((const float4*)(g_x1 + (size_t)warp * EMB))[q];
        const float inv3 = 1.0f / 3.0f;
        float4 o;
        o.x = (2.0f * x0v.x + 2.0f * x1v.x + dn * acc.x) * inv3;
        o.y = (2.0f * x0v.y + 2.0f * x1v.y + dn * acc.y) * inv3;
        o.z = (2.0f * x0v.z + 2.0f * x1v.z + dn * acc.z) * inv3;
        o.w = (2.0f * x0v.w + 2.0f * x1v.w + dn * acc.w) * inv3;
        ((float4*)(out + (size_t)warp * EMB))[q] = o;
    }
}

extern "C" void kernel_launch(void* const* d_in, const int* in_sizes, int n_in,
                              void* d_out, int out_size) {
    const float* u_emb = (const float*)d_in[0];
    const float* i_emb = (const float*)d_in[1];
    const int*   u_idx = (const int*)d_in[2];
    const int*   i_idx = (const int*)d_in[3];
    float*       out   = (float*)d_out;

    int NU = in_sizes[0] / EMB;
    int NI = in_sizes[1] / EMB;
    int E  = in_sizes[2];
    int N  = NU + NI;

    int nScanBlocks = (N + SCAN_B - 1) / SCAN_B;

    zero_deg_kernel<<<(N + 255) / 256, 256>>>(N);
    deg_kernel<<<(E + 255) / 256, 256>>>(u_idx, i_idx, E, NU);
    dis_kernel<<<(N + 255) / 256, 256>>>(N);

    scan1_kernel<<<nScanBlocks, SCAN_B>>>(N);
    scan2_kernel<<<1, MAX_SCAN_BLOCKS>>>(nScanBlocks);
    scan3_kernel<<<nScanBlocks, SCAN_B>>>(N, 2 * E);

    fill_kernel<<<(E + 255) / 256, 256>>>(u_idx, i_idx, E, NU);

    {
        size_t threads_total = (size_t)N * 32;
        int blocks = (int)((threads_total + 255) / 256);
        pull1_kernel<<<blocks, 256>>>(u_emb, i_emb, N, NU);
        pull2_kernel<<<blocks, 256>>>(u_emb, i_emb, out, N, NU);
    }
}

// round 5
// speedup vs baseline: 2.1862x; 1.0121x over previous
#include <cuda_runtime.h>
#include <cstdint>

// LightGCN 2-hop smoothing, pull-based SpMM over an on-the-fly CSR.
// N = NU + NI (200k), d = 64, E = 1.25M undirected (2.5M directed).
// out = (2*x0 + 2*x1 + x2)/3, x1 = S x0, x2 = S x1, S = D^-1/2 A D^-1/2.

#define EMB 64
#define MAX_NODES 200000
#define MAX_DEDGES 2500000
#define SCAN_B 256
#define MAX_SCAN_BLOCKS 1024   // ceil(200000/256) = 782

__device__ int   g_deg[MAX_NODES];
__device__ float g_dis[MAX_NODES];
__device__ int   g_row[MAX_NODES + 1];
__device__ int   g_cursor[MAX_NODES];
__device__ int   g_bsums[MAX_SCAN_BLOCKS];
__device__ int   g_boff[MAX_SCAN_BLOCKS];
__device__ int   g_adj[MAX_DEDGES];
__device__ float g_x1[(size_t)MAX_NODES * EMB];

__global__ void zero_deg_kernel(int N) {
    int n = blockIdx.x * blockDim.x + threadIdx.x;
    if (n < N) g_deg[n] = 0;
}

__global__ void deg_kernel(const int* __restrict__ u_idx,
                           const int* __restrict__ i_idx,
                           int E, int NU) {
    int e = blockIdx.x * blockDim.x + threadIdx.x;
    if (e < E) {
        atomicAdd(&g_deg[u_idx[e]], 1);
        atomicAdd(&g_deg[NU + i_idx[e]], 1);
    }
}

// ---- prefix scan (exclusive) of g_deg into g_row; also computes g_dis ----

__global__ void scan1_kernel(int N) {
    __shared__ int sh[SCAN_B];
    int t = threadIdx.x;
    int idx = blockIdx.x * SCAN_B + t;
    int v = (idx < N) ? g_deg[idx] : 0;
    if (idx < N) g_dis[idx] = (v > 0) ? rsqrtf((float)v) : 0.0f;
    sh[t] = v;
    __syncthreads();
    for (int off = 1; off < SCAN_B; off <<= 1) {
        int tmp = (t >= off) ? sh[t - off] : 0;
        __syncthreads();
        sh[t] += tmp;
        __syncthreads();
    }
    int incl = sh[t];
    if (idx < N) g_row[idx] = incl - v;   // block-local exclusive
    if (t == SCAN_B - 1) g_bsums[blockIdx.x] = incl;
}

__global__ void scan2_kernel(int nblocks) {
    __shared__ int sh[MAX_SCAN_BLOCKS];
    int t = threadIdx.x;
    int v = (t < nblocks) ? g_bsums[t] : 0;
    sh[t] = v;
    __syncthreads();
    for (int off = 1; off < MAX_SCAN_BLOCKS; off <<= 1) {
        int tmp = (t >= off) ? sh[t - off] : 0;
        __syncthreads();
        sh[t] += tmp;
        __syncthreads();
    }
    if (t < nblocks) g_boff[t] = sh[t] - v;  // exclusive
}

__global__ void scan3_kernel(int N, int twoE) {
    int idx = blockIdx.x * SCAN_B + threadIdx.x;
    if (idx < N) {
        int r = g_row[idx] + g_boff[blockIdx.x];
        g_row[idx] = r;
        g_cursor[idx] = r;
    }
    if (idx == 0) g_row[N] = twoE;
}

__global__ void fill_kernel(const int* __restrict__ u_idx,
                            const int* __restrict__ i_idx,
                            int E, int NU) {
    int e = blockIdx.x * blockDim.x + threadIdx.x;
    if (e < E) {
        int u = u_idx[e];
        int g = NU + i_idx[e];
        g_adj[atomicAdd(&g_cursor[g], 1)] = u;
        g_adj[atomicAdd(&g_cursor[u], 1)] = g;
    }
}

// ---- pull pass 1: x1 = S x0 ----
// One warp per node. Half-warps process different neighbors; each lane holds
// one float4 (16 lanes x 16B = full 256B row). Main loop: 8 neighbors/warp-iter
// -> 4 independent float4 gathers in flight per lane (MLP=4).
__global__ void pull1_kernel(const float* __restrict__ u_emb,
                             const float* __restrict__ i_emb,
                             int N, int NU) {
    int warp = (int)(((size_t)blockIdx.x * blockDim.x + threadIdx.x) >> 5);
    int lane = threadIdx.x & 31;
    if (warp >= N) return;

    int half = lane >> 4;
    int q    = lane & 15;

    int start = g_row[warp];
    int end   = g_row[warp + 1];

    float4 acc = make_float4(0.f, 0.f, 0.f, 0.f);
    int k = start;

    for (; k + 7 < end; k += 8) {
        int s0 = g_adj[k     + half];
        int s1 = g_adj[k + 2 + half];
        int s2 = g_adj[k + 4 + half];
        int s3 = g_adj[k + 6 + half];
        float w0 = g_dis[s0], w1 = g_dis[s1], w2 = g_dis[s2], w3 = g_dis[s3];
        const float4* p0 = (s0 < NU) ? (const float4*)(u_emb + (size_t)s0 * EMB)
                                     : (const float4*)(i_emb + (size_t)(s0 - NU) * EMB);
        const float4* p1 = (s1 < NU) ? (const float4*)(u_emb + (size_t)s1 * EMB)
                                     : (const float4*)(i_emb + (size_t)(s1 - NU) * EMB);
        const float4* p2 = (s2 < NU) ? (const float4*)(u_emb + (size_t)s2 * EMB)
                                     : (const float4*)(i_emb + (size_t)(s2 - NU) * EMB);
        const float4* p3 = (s3 < NU) ? (const float4*)(u_emb + (size_t)s3 * EMB)
                                     : (const float4*)(i_emb + (size_t)(s3 - NU) * EMB);
        float4 v0 = p0[q], v1 = p1[q], v2 = p2[q], v3 = p3[q];
        acc.x += w0 * v0.x + w1 * v1.x + w2 * v2.x + w3 * v3.x;
        acc.y += w0 * v0.y + w1 * v1.y + w2 * v2.y + w3 * v3.y;
        acc.z += w0 * v0.z + w1 * v1.z + w2 * v2.z + w3 * v3.z;
        acc.w += w0 * v0.w + w1 * v1.w + w2 * v2.w + w3 * v3.w;
    }
    for (; k + 1 < end; k += 2) {
        int s = g_adj[k + half];
        float w = g_dis[s];
        const float4* p = (s < NU) ? (const float4*)(u_emb + (size_t)s * EMB)
                                   : (const float4*)(i_emb + (size_t)(s - NU) * EMB);
        float4 v = p[q];
        acc.x += w * v.x; acc.y += w * v.y; acc.z += w * v.z; acc.w += w * v.w;
    }
    if (k < end && half == 0) {
        int s = g_adj[k];
        float w = g_dis[s];
        const float4* p = (s < NU) ? (const float4*)(u_emb + (size_t)s * EMB)
                                   : (const float4*)(i_emb + (size_t)(s - NU) * EMB);
        float4 v = p[q];
        acc.x += w * v.x; acc.y += w * v.y; acc.z += w * v.z; acc.w += w * v.w;
    }

    acc.x += __shfl_xor_sync(0xffffffffu, acc.x, 16);
    acc.y += __shfl_xor_sync(0xffffffffu, acc.y, 16);
    acc.z += __shfl_xor_sync(0xffffffffu, acc.z, 16);
    acc.w += __shfl_xor_sync(0xffffffffu, acc.w, 16);

    if (half == 0) {
        float dn = g_dis[warp];
        float4 o = make_float4(dn * acc.x, dn * acc.y, dn * acc.z, dn * acc.w);
        ((float4*)(g_x1 + (size_t)warp * EMB))[q] = o;
    }
}

// ---- pull pass 2 fused with output combine ----
// out[n] = (2*x0[n] + 2*x1[n] + dis[n]*sum dis[s]*x1[s]) / 3
__global__ void pull2_kernel(const float* __restrict__ u_emb,
                             const float* __restrict__ i_emb,
                             float* __restrict__ out,
                             int N, int NU) {
    int warp = (int)(((size_t)blockIdx.x * blockDim.x + threadIdx.x) >> 5);
    int lane = threadIdx.x & 31;
    if (warp >= N) return;

    int half = lane >> 4;
    int q    = lane & 15;

    int start = g_row[warp];
    int end   = g_row[warp + 1];

    float4 acc = make_float4(0.f, 0.f, 0.f, 0.f);
    int k = start;

    for (; k + 7 < end; k += 8) {
        int s0 = g_adj[k     + half];
        int s1 = g_adj[k + 2 + half];
        int s2 = g_adj[k + 4 + half];
        int s3 = g_adj[k + 6 + half];
        float w0 = g_dis[s0], w1 = g_dis[s1], w2 = g_dis[s2], w3 = g_dis[s3];
        float4 v0 = ((const float4*)(g_x1 + (size_t)s0 * EMB))[q];
        float4 v1 = ((const float4*)(g_x1 + (size_t)s1 * EMB))[q];
        float4 v2 = ((const float4*)(g_x1 + (size_t)s2 * EMB))[q];
        float4 v3 = ((const float4*)(g_x1 + (size_t)s3 * EMB))[q];
        acc.x += w0 * v0.x + w1 * v1.x + w2 * v2.x + w3 * v3.x;
        acc.y += w0 * v0.y + w1 * v1.y + w2 * v2.y + w3 * v3.y;
        acc.z += w0 * v0.z + w1 * v1.z + w2 * v2.z + w3 * v3.z;
        acc.w += w0 * v0.w + w1 * v1.w + w2 * v2.w + w3 * v3.w;
    }
    for (; k + 1 < end; k += 2) {
        int s = g_adj[k + half];
        float w = g_dis[s];
        float4 v = ((const float4*)(g_x1 + (size_t)s * EMB))[q];
        acc.x += w * v.x; acc.y += w * v.y; acc.z += w * v.z; acc.w += w * v.w;
    }
    if (k < end && half == 0) {
        int s = g_adj[k];
        float w = g_dis[s];
        float4 v = ((const float4*)(g_x1 + (size_t)s * EMB))[q];
        acc.x += w * v.x; acc.y += w * v.y; acc.z += w * v.z; acc.w += w * v.w;
    }

    acc.x += __shfl_xor_sync(0xffffffffu, acc.x, 16);
    acc.y += __shfl_xor_sync(0xffffffffu, acc.y, 16);
    acc.z += __shfl_xor_sync(0xffffffffu, acc.z, 16);
    acc.w += __shfl_xor_sync(0xffffffffu, acc.w, 16);

    if (half == 0) {
        float dn = g_dis[warp];
        const float4* x0b = (warp < NU)
            ? (const float4*)(u_emb + (size_t)warp * EMB)
            : (const float4*)(i_emb + (size_t)(warp - NU) * EMB);
        float4 x0v = x0b[q];
        float4 x1v = ((const float4*)(g_x1 + (size_t)warp * EMB))[q];
        const float inv3 = 1.0f / 3.0f;
        float4 o;
        o.x = (2.0f * x0v.x + 2.0f * x1v.x + dn * acc.x) * inv3;
        o.y = (2.0f * x0v.y + 2.0f * x1v.y + dn * acc.y) * inv3;
        o.z = (2.0f * x0v.z + 2.0f * x1v.z + dn * acc.z) * inv3;
        o.w = (2.0f * x0v.w + 2.0f * x1v.w + dn * acc.w) * inv3;
        ((float4*)(out + (size_t)warp * EMB))[q] = o;
    }
}

extern "C" void kernel_launch(void* const* d_in, const int* in_sizes, int n_in,
                              void* d_out, int out_size) {
    const float* u_emb = (const float*)d_in[0];
    const float* i_emb = (const float*)d_in[1];
    const int*   u_idx = (const int*)d_in[2];
    const int*   i_idx = (const int*)d_in[3];
    float*       out   = (float*)d_out;

    int NU = in_sizes[0] / EMB;
    int NI = in_sizes[1] / EMB;
    int E  = in_sizes[2];
    int N  = NU + NI;

    int nScanBlocks = (N + SCAN_B - 1) / SCAN_B;

    zero_deg_kernel<<<(N + 255) / 256, 256>>>(N);
    deg_kernel<<<(E + 255) / 256, 256>>>(u_idx, i_idx, E, NU);

    scan1_kernel<<<nScanBlocks, SCAN_B>>>(N);
    scan2_kernel<<<1, MAX_SCAN_BLOCKS>>>(nScanBlocks);
    scan3_kernel<<<nScanBlocks, SCAN_B>>>(N, 2 * E);

    fill_kernel<<<(E + 255) / 256, 256>>>(u_idx, i_idx, E, NU);

    {
        size_t threads_total = (size_t)N * 32;
        int blocks = (int)((threads_total + 255) / 256);
        pull1_kernel<<<blocks, 256>>>(u_emb, i_emb, N, NU);
        pull2_kernel<<<blocks, 256>>>(u_emb, i_emb, out, N, NU);
    }
}